// round 9
// baseline (speedup 1.0000x reference)
#include <cuda_runtime.h>
#include <cstdint>
#include <cstddef>

// ---------------------------------------------------------------------------
// Problem dims (fixed by the reference)
// ---------------------------------------------------------------------------
#define Bb   2
#define Ss   4096
#define Ff   768
#define Hh   12
#define Dd   64
#define ROWS (Bb * Ss)          // 8192 token rows
#define NQKV (3 * Ff)           // 2304

// ---------------------------------------------------------------------------
// Scratch (device globals: allocation-free rule)
// ---------------------------------------------------------------------------
__device__ float g_q[ROWS * Ff];     // [B,S,H,D] flattened
__device__ float g_k[ROWS * Ff];
__device__ float g_v[ROWS * Ff];
__device__ float g_attn[ROWS * Ff];  // attention output [B,S,H,D]

// ---------------------------------------------------------------------------
// TF32 / cp.async helpers
// ---------------------------------------------------------------------------
__device__ __forceinline__ unsigned f2tf(float f) {
    unsigned u;
    asm("cvt.rna.tf32.f32 %0, %1;" : "=r"(u) : "f"(f));
    return u;
}

// D += A(16x8) * B(8x8), tf32 inputs, fp32 accum
__device__ __forceinline__ void mma8(float* c, const unsigned* a, const unsigned* b) {
    asm volatile(
        "mma.sync.aligned.m16n8k8.row.col.f32.tf32.tf32.f32 "
        "{%0,%1,%2,%3}, {%4,%5,%6,%7}, {%8,%9}, {%0,%1,%2,%3};"
        : "+f"(c[0]), "+f"(c[1]), "+f"(c[2]), "+f"(c[3])
        : "r"(a[0]), "r"(a[1]), "r"(a[2]), "r"(a[3]), "r"(b[0]), "r"(b[1]));
}

__device__ __forceinline__ void cp16(void* dst, const void* src) {
    unsigned d = (unsigned)__cvta_generic_to_shared(dst);
    asm volatile("cp.async.cg.shared.global [%0], [%1], 16;" :: "r"(d), "l"(src));
}
__device__ __forceinline__ void cpcommit() {
    asm volatile("cp.async.commit_group;" ::: "memory");
}
__device__ __forceinline__ void cpwait0() {
    asm volatile("cp.async.wait_group 0;" ::: "memory");
}

// ---------------------------------------------------------------------------
// Kernel 1 & 3: TF32 tensor-core GEMM, 128x128 tile, BK=16, double-buffered,
// ONE __syncthreads per 16-K iteration. 256 threads; warps 2(M)x4(N);
// per warp 4x4 m16n8 tiles, 2 k-subtiles per iteration.
// As[m][k] pitch 20 (20*gid+tig distinct mod 32 -> conflict-free frag loads),
// Bs[k][n] pitch 136 (8*tig+n distinct -> conflict-free).
// mode 0: split columns into g_q/g_k/g_v (N==2304); mode 1: C = acc + bias.
// ---------------------------------------------------------------------------
__global__ __launch_bounds__(256)
void gemm_tf32(const float* __restrict__ A, const float* __restrict__ Bm,
               const float* __restrict__ bias, float* __restrict__ C,
               int K, int N, int mode)
{
    __shared__ unsigned As[2][128][20];
    __shared__ unsigned Bs[2][16][136];

    const int tid  = threadIdx.x;
    const int lane = tid & 31;
    const int wid  = tid >> 5;
    const int gid  = lane >> 2;      // 0..7
    const int tig  = lane & 3;       // 0..3
    const int warpM = wid & 1;
    const int warpN = wid >> 1;

    const int rowBase = blockIdx.y * 128;
    const int colBase = blockIdx.x * 128;

    // loaders: A 128 rows x 16 k (2 float4/thread), B 16 k x 128 cols (2 float4)
    const int aRow = tid >> 1;
    const int aCol = (tid & 1) * 4;
    const int bRow = tid >> 5;
    const int bCol = (tid & 31) * 4;
    const float* Aptr = A + (size_t)(rowBase + aRow) * K + aCol;
    const float* Bptr = Bm + (size_t)bRow * N + colBase + bCol;

    float acc[4][4][4];
#pragma unroll
    for (int mt = 0; mt < 4; mt++)
#pragma unroll
        for (int nt = 0; nt < 4; nt++)
#pragma unroll
            for (int r = 0; r < 4; r++) acc[mt][nt][r] = 0.f;

    // ---- preload tile 0 into buffer 0 ----
    {
        float4 a0 = *(const float4*)Aptr;
        float4 a1 = *(const float4*)(Aptr + 8);
        float4 b0 = *(const float4*)Bptr;
        float4 b1 = *(const float4*)(Bptr + (size_t)8 * N);
        As[0][aRow][aCol + 0] = f2tf(a0.x); As[0][aRow][aCol + 1] = f2tf(a0.y);
        As[0][aRow][aCol + 2] = f2tf(a0.z); As[0][aRow][aCol + 3] = f2tf(a0.w);
        As[0][aRow][aCol + 8] = f2tf(a1.x); As[0][aRow][aCol + 9] = f2tf(a1.y);
        As[0][aRow][aCol + 10] = f2tf(a1.z); As[0][aRow][aCol + 11] = f2tf(a1.w);
        *(uint4*)&Bs[0][bRow][bCol] =
            make_uint4(f2tf(b0.x), f2tf(b0.y), f2tf(b0.z), f2tf(b0.w));
        *(uint4*)&Bs[0][bRow + 8][bCol] =
            make_uint4(f2tf(b1.x), f2tf(b1.y), f2tf(b1.z), f2tf(b1.w));
    }
    __syncthreads();

    const int nIter = K / 16;
#pragma unroll 1
    for (int it = 0; it < nIter; it++) {
        const int cur = it & 1;
        const bool more = (it + 1 < nIter);
        float4 na0, na1, nb0, nb1;
        if (more) {
            const int k0 = (it + 1) * 16;
            na0 = *(const float4*)(Aptr + k0);
            na1 = *(const float4*)(Aptr + k0 + 8);
            nb0 = *(const float4*)(Bptr + (size_t)k0 * N);
            nb1 = *(const float4*)(Bptr + (size_t)(k0 + 8) * N);
        }

        // ---- compute both k-subtiles from buffer cur ----
#pragma unroll
        for (int ks = 0; ks < 2; ks++) {
            unsigned af[4][4], bf[4][2];
#pragma unroll
            for (int mt = 0; mt < 4; mt++) {
                const int m = warpM * 64 + mt * 16 + gid;
                af[mt][0] = As[cur][m][8 * ks + tig];
                af[mt][1] = As[cur][m + 8][8 * ks + tig];
                af[mt][2] = As[cur][m][8 * ks + tig + 4];
                af[mt][3] = As[cur][m + 8][8 * ks + tig + 4];
            }
#pragma unroll
            for (int nt = 0; nt < 4; nt++) {
                const int n = warpN * 32 + nt * 8 + gid;
                bf[nt][0] = Bs[cur][8 * ks + tig][n];
                bf[nt][1] = Bs[cur][8 * ks + tig + 4][n];
            }
#pragma unroll
            for (int mt = 0; mt < 4; mt++)
#pragma unroll
                for (int nt = 0; nt < 4; nt++)
                    mma8(acc[mt][nt], af[mt], bf[nt]);
        }

        // ---- stage next tile into the other buffer ----
        if (more) {
            const int nxt = cur ^ 1;
            As[nxt][aRow][aCol + 0] = f2tf(na0.x); As[nxt][aRow][aCol + 1] = f2tf(na0.y);
            As[nxt][aRow][aCol + 2] = f2tf(na0.z); As[nxt][aRow][aCol + 3] = f2tf(na0.w);
            As[nxt][aRow][aCol + 8] = f2tf(na1.x); As[nxt][aRow][aCol + 9] = f2tf(na1.y);
            As[nxt][aRow][aCol + 10] = f2tf(na1.z); As[nxt][aRow][aCol + 11] = f2tf(na1.w);
            *(uint4*)&Bs[nxt][bRow][bCol] =
                make_uint4(f2tf(nb0.x), f2tf(nb0.y), f2tf(nb0.z), f2tf(nb0.w));
            *(uint4*)&Bs[nxt][bRow + 8][bCol] =
                make_uint4(f2tf(nb1.x), f2tf(nb1.y), f2tf(nb1.z), f2tf(nb1.w));
        }
        __syncthreads();
    }

    // ---- epilogue ----
#pragma unroll
    for (int mt = 0; mt < 4; mt++) {
        const int m0 = rowBase + warpM * 64 + mt * 16 + gid;
#pragma unroll
        for (int nt = 0; nt < 4; nt++) {
            const int n = colBase + warpN * 32 + nt * 8 + 2 * tig;
            const float b0 = bias[n];
            const float b1 = bias[n + 1];
            if (mode == 0) {
                const int seg = n / Ff;              // 0:q 1:k 2:v
                float* dst = (seg == 0) ? g_q : (seg == 1) ? g_k : g_v;
                const int ln = n - seg * Ff;
                *(float2*)(dst + (size_t)m0 * Ff + ln) =
                    make_float2(acc[mt][nt][0] + b0, acc[mt][nt][1] + b1);
                *(float2*)(dst + (size_t)(m0 + 8) * Ff + ln) =
                    make_float2(acc[mt][nt][2] + b0, acc[mt][nt][3] + b1);
            } else {
                *(float2*)(C + (size_t)m0 * N + n) =
                    make_float2(acc[mt][nt][0] + b0, acc[mt][nt][1] + b1);
                *(float2*)(C + (size_t)(m0 + 8) * N + n) =
                    make_float2(acc[mt][nt][2] + b0, acc[mt][nt][3] + b1);
            }
        }
    }
}

// ---------------------------------------------------------------------------
// Kernel 2: TF32 flash attention, causal, cp.async-pipelined.
// CTA: 128 q-rows, 8 warps (16 q-rows each), 64-key tiles, D=64.
// Per tile: wait(staged raw K/V/pad) -> convert to frag smem -> issue cp.async
// for the NEXT tile -> compute. GMEM latency overlaps compute.
// Frag pitches: Ks/Ps 68, Vs 72 (conflict-free frag LDS). Staging pitch 68.
// ---------------------------------------------------------------------------
#define APQ 68
#define APV 72
#define KST 68
// u32 units: Ks + Vs + Ps + Kst + Vst + padAdd + padRaw
#define FLASH_SMEM_U32 (64*APQ + 64*APV + 8*16*APQ + 64*KST + 64*KST + 64 + 16)
#define FLASH_SMEM_BYTES (FLASH_SMEM_U32 * 4)

__device__ __forceinline__ void flash_issue_tile(
    float* Kst, float* Vst, unsigned* padRaw,
    const float* Kg, const float* Vg, const unsigned char* pm,
    int kBase, int tid)
{
#pragma unroll
    for (int i = 0; i < 4; i++) {
        const int idx = tid + 256 * i;       // 0..1023
        const int r   = idx >> 4;            // 0..63
        const int c4  = (idx & 15) * 4;
        cp16(Kst + r * KST + c4, Kg + (size_t)(kBase + r) * Ff + c4);
        cp16(Vst + r * KST + c4, Vg + (size_t)(kBase + r) * Ff + c4);
    }
    if (tid < 4)
        cp16(padRaw + tid * 4, pm + kBase + tid * 16);
    cpcommit();
}

__global__ __launch_bounds__(256, 2)
void flash_tf32(const unsigned char* __restrict__ padmask)
{
    extern __shared__ unsigned sm[];
    unsigned* Ks   = sm;                         // [64][APQ] tf32 frags
    unsigned* Vs   = Ks + 64 * APQ;              // [64][APV]
    unsigned* Ps   = Vs + 64 * APV;              // [8 warps][16][APQ]
    float*    Kst  = (float*)(Ps + 8 * 16 * APQ);// [64][KST] raw staging
    float*    Vst  = Kst + 64 * KST;
    float*    padAdd = Vst + 64 * KST;           // [64]
    unsigned* padRaw = (unsigned*)(padAdd + 64); // [16] (64 bytes)

    const int tid  = threadIdx.x;
    const int lane = tid & 31;
    const int w    = tid >> 5;
    const int gid  = lane >> 2;
    const int tig  = lane & 3;

    const int bh = blockIdx.y;
    const int b  = bh / Hh;
    const int h  = bh % Hh;
    const int qt = gridDim.x - 1 - blockIdx.x;      // longest CTAs first
    const int qBase = qt * 128;
    const int qRow0 = qBase + w * 16;

    const float* Qg = g_q + (size_t)b * Ss * Ff + h * Dd;
    const float* Kg = g_k + (size_t)b * Ss * Ff + h * Dd;
    const float* Vg = g_v + (size_t)b * Ss * Ff + h * Dd;
    const unsigned char* pm = padmask + (size_t)b * Ss;

    unsigned* Pw = Ps + w * 16 * APQ;

    // ---- kick off tile 0 staging ASAP, overlap with Q prologue ----
    flash_issue_tile(Kst, Vst, padRaw, Kg, Vg, pm, 0, tid);

    // ---- prologue: build Q a-fragments in registers (scale folded) ----
    const float QSCALE = 0.125f * 1.4426950408889634f;   // 1/sqrt(D) * log2(e)
#pragma unroll
    for (int i = 0; i < 8; i++) {
        const int idx = lane + 32 * i;          // 0..255
        const int r   = idx >> 4;               // 0..15
        const int c4  = (idx & 15) * 4;
        float4 v = *(const float4*)(Qg + (size_t)(qRow0 + r) * Ff + c4);
        *(uint4*)&Pw[r * APQ + c4] =
            make_uint4(f2tf(v.x * QSCALE), f2tf(v.y * QSCALE),
                       f2tf(v.z * QSCALE), f2tf(v.w * QSCALE));
    }
    __syncwarp();
    unsigned qa[8][4];
#pragma unroll
    for (int t8 = 0; t8 < 8; t8++) {
        qa[t8][0] = Pw[gid * APQ + 8 * t8 + tig];
        qa[t8][1] = Pw[(gid + 8) * APQ + 8 * t8 + tig];
        qa[t8][2] = Pw[gid * APQ + 8 * t8 + tig + 4];
        qa[t8][3] = Pw[(gid + 8) * APQ + 8 * t8 + tig + 4];
    }

    float o[8][4];
#pragma unroll
    for (int j = 0; j < 8; j++)
#pragma unroll
        for (int r = 0; r < 4; r++) o[j][r] = 0.f;
    float mlo = -1e30f, mhi = -1e30f, llo = 0.f, lhi = 0.f;

    const int nkt = (qBase + 128) / 64;          // causal tile count
#pragma unroll 1
    for (int kt = 0; kt < nkt; kt++) {
        const int kBase = kt * 64;

        // ---- wait for staged raw tile; all warps past last compute ----
        cpwait0();
        __syncthreads();

        // ---- convert staging -> fragment-layout smem (L1-speed) ----
#pragma unroll
        for (int i = 0; i < 4; i++) {
            const int idx = tid + 256 * i;
            const int r   = idx >> 4;
            const int c4  = (idx & 15) * 4;
            float4 kv = *(const float4*)&Kst[r * KST + c4];
            *(uint4*)&Ks[r * APQ + c4] =
                make_uint4(f2tf(kv.x), f2tf(kv.y), f2tf(kv.z), f2tf(kv.w));
            float4 vv = *(const float4*)&Vst[r * KST + c4];
            *(uint4*)&Vs[r * APV + c4] =
                make_uint4(f2tf(vv.x), f2tf(vv.y), f2tf(vv.z), f2tf(vv.w));
        }
        if (tid < 64)
            padAdd[tid] = ((const unsigned char*)padRaw)[tid] ? -1e30f : 0.f;
        __syncthreads();

        // ---- prefetch next tile: overlaps the whole compute phase ----
        if (kt + 1 < nkt)
            flash_issue_tile(Kst, Vst, padRaw, Kg, Vg, pm, kBase + 64, tid);

        // warps fully above the diagonal for this key tile do nothing
        const bool active = (kBase <= qRow0 + 15);
        if (active) {
            // ---- S = Q K^T (scaled, log2 domain) ----
            float s[8][4];
#pragma unroll
            for (int j = 0; j < 8; j++)
#pragma unroll
                for (int r = 0; r < 4; r++) s[j][r] = 0.f;

#pragma unroll
            for (int t8 = 0; t8 < 8; t8++) {
#pragma unroll
                for (int j = 0; j < 8; j++) {
                    unsigned bfr[2];
                    bfr[0] = Ks[(8 * j + gid) * APQ + 8 * t8 + tig];
                    bfr[1] = Ks[(8 * j + gid) * APQ + 8 * t8 + tig + 4];
                    mma8(s[j], qa[t8], bfr);
                }
            }

            // ---- padding + causal mask ----
            const int qlo = qRow0 + gid;
            const int qhi = qlo + 8;
            if (kBase + 63 > qRow0) {            // warp-uniform: diagonal tile
#pragma unroll
                for (int j = 0; j < 8; j++) {
                    const float pv0 = padAdd[8 * j + 2 * tig];
                    const float pv1 = padAdd[8 * j + 2 * tig + 1];
                    const int k0 = kBase + 8 * j + 2 * tig;
                    const int k1 = k0 + 1;
                    s[j][0] = (k0 > qlo) ? -1e30f : s[j][0] + pv0;
                    s[j][1] = (k1 > qlo) ? -1e30f : s[j][1] + pv1;
                    s[j][2] = (k0 > qhi) ? -1e30f : s[j][2] + pv0;
                    s[j][3] = (k1 > qhi) ? -1e30f : s[j][3] + pv1;
                }
            } else {
#pragma unroll
                for (int j = 0; j < 8; j++) {
                    const float pv0 = padAdd[8 * j + 2 * tig];
                    const float pv1 = padAdd[8 * j + 2 * tig + 1];
                    s[j][0] += pv0; s[j][1] += pv1;
                    s[j][2] += pv0; s[j][3] += pv1;
                }
            }

            // ---- online softmax (rows owned by 4-lane quads) ----
            float mtlo = -1e30f, mthi = -1e30f;
#pragma unroll
            for (int j = 0; j < 8; j++) {
                mtlo = fmaxf(mtlo, fmaxf(s[j][0], s[j][1]));
                mthi = fmaxf(mthi, fmaxf(s[j][2], s[j][3]));
            }
            mtlo = fmaxf(mtlo, __shfl_xor_sync(0xffffffffu, mtlo, 1));
            mtlo = fmaxf(mtlo, __shfl_xor_sync(0xffffffffu, mtlo, 2));
            mthi = fmaxf(mthi, __shfl_xor_sync(0xffffffffu, mthi, 1));
            mthi = fmaxf(mthi, __shfl_xor_sync(0xffffffffu, mthi, 2));

            const float mnl = fmaxf(mlo, mtlo);
            const float mnh = fmaxf(mhi, mthi);
            const float clo = exp2f(mlo - mnl);
            const float chi = exp2f(mhi - mnh);
            mlo = mnl; mhi = mnh;

            float rslo = 0.f, rshi = 0.f;
#pragma unroll
            for (int j = 0; j < 8; j++) {
                s[j][0] = exp2f(s[j][0] - mnl);
                s[j][1] = exp2f(s[j][1] - mnl);
                s[j][2] = exp2f(s[j][2] - mnh);
                s[j][3] = exp2f(s[j][3] - mnh);
                rslo += s[j][0] + s[j][1];
                rshi += s[j][2] + s[j][3];
            }
            rslo += __shfl_xor_sync(0xffffffffu, rslo, 1);
            rslo += __shfl_xor_sync(0xffffffffu, rslo, 2);
            rshi += __shfl_xor_sync(0xffffffffu, rshi, 1);
            rshi += __shfl_xor_sync(0xffffffffu, rshi, 2);
            llo = llo * clo + rslo;
            lhi = lhi * chi + rshi;
#pragma unroll
            for (int j = 0; j < 8; j++) {
                o[j][0] *= clo; o[j][1] *= clo;
                o[j][2] *= chi; o[j][3] *= chi;
            }

            // ---- P d-frag -> per-warp smem -> a-frag; O += P V ----
#pragma unroll
            for (int j = 0; j < 8; j++) {
                *(uint2*)&Pw[gid * APQ + 8 * j + 2 * tig] =
                    make_uint2(f2tf(s[j][0]), f2tf(s[j][1]));
                *(uint2*)&Pw[(gid + 8) * APQ + 8 * j + 2 * tig] =
                    make_uint2(f2tf(s[j][2]), f2tf(s[j][3]));
            }
            __syncwarp();
#pragma unroll
            for (int t8 = 0; t8 < 8; t8++) {
                unsigned pa[4];
                pa[0] = Pw[gid * APQ + 8 * t8 + tig];
                pa[1] = Pw[(gid + 8) * APQ + 8 * t8 + tig];
                pa[2] = Pw[gid * APQ + 8 * t8 + tig + 4];
                pa[3] = Pw[(gid + 8) * APQ + 8 * t8 + tig + 4];
#pragma unroll
                for (int j = 0; j < 8; j++) {
                    unsigned bfr[2];
                    bfr[0] = Vs[(8 * t8 + tig) * APV + 8 * j + gid];
                    bfr[1] = Vs[(8 * t8 + tig + 4) * APV + 8 * j + gid];
                    mma8(o[j], pa, bfr);
                }
            }
        }
    }

    // ---- finalize: O /= l, write [B,S,H,D] ----
    const float ilo = 1.0f / llo;
    const float ihi = 1.0f / lhi;
    const int qlo = qRow0 + gid;
    float* Og = g_attn + (size_t)b * Ss * Ff + h * Dd;
#pragma unroll
    for (int j = 0; j < 8; j++) {
        const int d = 8 * j + 2 * tig;
        *(float2*)(Og + (size_t)qlo * Ff + d) =
            make_float2(o[j][0] * ilo, o[j][1] * ilo);
        *(float2*)(Og + (size_t)(qlo + 8) * Ff + d) =
            make_float2(o[j][2] * ihi, o[j][3] * ihi);
    }
}

// ---------------------------------------------------------------------------
// Launch: QKV gemm -> flash attention -> output gemm (one default stream)
// ---------------------------------------------------------------------------
extern "C" void kernel_launch(void* const* d_in, const int* in_sizes, int n_in,
                              void* d_out, int out_size)
{
    (void)in_sizes; (void)n_in; (void)out_size;
    const float*         x    = (const float*)d_in[0];
    const unsigned char* pad  = (const unsigned char*)d_in[1];
    const float*         Wqkv = (const float*)d_in[2];
    const float*         bqkv = (const float*)d_in[3];
    const float*         Wout = (const float*)d_in[4];
    const float*         bout = (const float*)d_in[5];
    float*               out  = (float*)d_out;

    // 1) QKV projection (tf32): [8192,768] @ [768,2304] -> g_q/g_k/g_v
    {
        dim3 grid(NQKV / 128, ROWS / 128);   // (18, 64)
        gemm_tf32<<<grid, 256>>>(x, Wqkv, bqkv, nullptr, Ff, NQKV, 0);
    }

    // 2) causal flash attention (tf32 mma, cp.async pipelined) -> g_attn
    {
        cudaFuncSetAttribute(flash_tf32,
                             cudaFuncAttributeMaxDynamicSharedMemorySize,
                             FLASH_SMEM_BYTES);
        dim3 grid(Ss / 128, Bb * Hh);        // (32, 24)
        flash_tf32<<<grid, 256, FLASH_SMEM_BYTES>>>(pad);
    }

    // 3) output projection (tf32): g_attn @ Wout + bout -> d_out
    {
        float* attnPtr = nullptr;
        cudaGetSymbolAddress((void**)&attnPtr, g_attn);
        dim3 grid(Ff / 128, ROWS / 128);     // (6, 64)
        gemm_tf32<<<grid, 256>>>(attnPtr, Wout, bout, out, Ff, Ff, 1);
    }
}

// round 11
// speedup vs baseline: 1.9530x; 1.9530x over previous
#include <cuda_runtime.h>
#include <cuda_fp16.h>
#include <cstdint>
#include <cstddef>

// ---------------------------------------------------------------------------
// Problem dims (fixed by the reference)
// ---------------------------------------------------------------------------
#define Bb   2
#define Ss   4096
#define Ff   768
#define Hh   12
#define Dd   64
#define ROWS (Bb * Ss)          // 8192 token rows
#define NQKV (3 * Ff)           // 2304

// ---------------------------------------------------------------------------
// Scratch (device globals: allocation-free rule). All intermediates fp16.
// ---------------------------------------------------------------------------
__device__ __half g_xh[ROWS * Ff];     // x converted to fp16
__device__ __half g_q[ROWS * Ff];      // [B,S,H,D]
__device__ __half g_k[ROWS * Ff];
__device__ __half g_v[ROWS * Ff];
__device__ __half g_attn[ROWS * Ff];   // attention output [B,S,H,D]
__device__ __half g_WqkvT[NQKV * Ff];  // Wqkv^T [2304][768] fp16
__device__ __half g_WoutT[Ff * Ff];    // Wout^T [768][768] fp16

// ---------------------------------------------------------------------------
// Helpers
// ---------------------------------------------------------------------------
__device__ __forceinline__ unsigned pack2(float a, float b) {
    __half2 h = __floats2half2_rn(a, b);       // .x = a (lo), .y = b (hi)
    return *reinterpret_cast<unsigned*>(&h);
}

// D(16x8,f32) += A(16x16,f16) * B(16x8,f16)
__device__ __forceinline__ void mma16(float* c, const unsigned* a,
                                      unsigned b0, unsigned b1) {
    asm volatile(
        "mma.sync.aligned.m16n8k16.row.col.f32.f16.f16.f32 "
        "{%0,%1,%2,%3}, {%4,%5,%6,%7}, {%8,%9}, {%0,%1,%2,%3};"
        : "+f"(c[0]), "+f"(c[1]), "+f"(c[2]), "+f"(c[3])
        : "r"(a[0]), "r"(a[1]), "r"(a[2]), "r"(a[3]), "r"(b0), "r"(b1));
}

#define LDSM_X4_T(r0, r1, r2, r3, addr)                                       \
    asm volatile(                                                             \
        "ldmatrix.sync.aligned.m8n8.x4.trans.shared.b16 {%0,%1,%2,%3}, [%4];" \
        : "=r"(r0), "=r"(r1), "=r"(r2), "=r"(r3) : "r"(addr))

__device__ __forceinline__ uint32_t smem_u32(const void* p) {
    uint32_t a;
    asm("{ .reg .u64 t; cvta.to.shared.u64 t, %1; cvt.u32.u64 %0, t; }"
        : "=r"(a) : "l"(p));
    return a;
}

// ---------------------------------------------------------------------------
// Kernel A: float -> half bulk convert (for x)
// ---------------------------------------------------------------------------
__global__ __launch_bounds__(256)
void f2h_kernel(const float* __restrict__ s, __half* __restrict__ d)
{
    const size_t i = ((size_t)blockIdx.x * 256 + threadIdx.x) * 4;
    float4 v = *(const float4*)(s + i);
    *(uint2*)(d + i) = make_uint2(pack2(v.x, v.y), pack2(v.z, v.w));
}

// ---------------------------------------------------------------------------
// Kernel B: transpose W[K][N] (f32) -> WT[N][K] (f16)
// ---------------------------------------------------------------------------
__global__ __launch_bounds__(256)
void transpose_kn_h(const float* __restrict__ W, __half* __restrict__ WT,
                    int K, int N)
{
    __shared__ float t[32][33];
    const int tx = threadIdx.x & 31, ty = threadIdx.x >> 5;
    const int n0 = blockIdx.x * 32, k0 = blockIdx.y * 32;
#pragma unroll
    for (int i = 0; i < 4; i++)
        t[ty + 8 * i][tx] = W[(size_t)(k0 + ty + 8 * i) * N + n0 + tx];
    __syncthreads();
#pragma unroll
    for (int i = 0; i < 4; i++)
        WT[(size_t)(n0 + ty + 8 * i) * K + k0 + tx] =
            __float2half(t[tx][ty + 8 * i]);
}

// ---------------------------------------------------------------------------
// Kernel 1 & 3: FP16 m16n8k16 GEMM, 128x128 tile, BK=16, 256 threads.
// A[m][k] f16 row-major, BT[n][k] f16 row-major. Warps 2(M)x4(N), 4x4 tiles.
// Smem pitch 12 words (24 halves) per 16-half row -> fragment LDS
// conflict-free (gid*12+tig distinct mod 32).
// mode 0: C half, split into g_q/g_k/g_v (N==2304). mode 1: C float + bias.
// ---------------------------------------------------------------------------
__global__ __launch_bounds__(256, 2)
void gemm_h(const __half* __restrict__ A, const __half* __restrict__ BT,
            const float* __restrict__ bias, float* __restrict__ C,
            int K, int N, int mode)
{
    __shared__ unsigned As[128][12];
    __shared__ unsigned Bs[128][12];

    const int tid  = threadIdx.x;
    const int lane = tid & 31;
    const int wid  = tid >> 5;
    const int gid  = lane >> 2;      // 0..7
    const int tig  = lane & 3;       // 0..3
    const int warpM = wid & 1;
    const int warpN = wid >> 1;

    const int rowBase = blockIdx.y * 128;
    const int colBase = blockIdx.x * 128;

    // loaders: thread -> (row tid>>1, uint4 half tid&1); 1 uint4 per matrix
    const int aRow = tid >> 1;
    const int aC   = tid & 1;
    const __half* Ap = A  + (size_t)(rowBase + aRow) * K + aC * 8;
    const __half* Bp = BT + (size_t)(colBase + aRow) * K + aC * 8;

    float acc[4][4][4];
#pragma unroll
    for (int mt = 0; mt < 4; mt++)
#pragma unroll
        for (int nt = 0; nt < 4; nt++)
#pragma unroll
            for (int r = 0; r < 4; r++) acc[mt][nt][r] = 0.f;

    uint4 ra = *(const uint4*)Ap;
    uint4 rb = *(const uint4*)Bp;

    const int nIter = K / 16;
#pragma unroll 1
    for (int it = 0; it < nIter; it++) {
        *(uint4*)&As[aRow][aC * 4] = ra;
        *(uint4*)&Bs[aRow][aC * 4] = rb;
        __syncthreads();

        if (it + 1 < nIter) {
            ra = *(const uint4*)(Ap + (it + 1) * 16);
            rb = *(const uint4*)(Bp + (it + 1) * 16);
        }

        unsigned af[4][4], bf[4][2];
#pragma unroll
        for (int mt = 0; mt < 4; mt++) {
            const int m = warpM * 64 + mt * 16 + gid;
            af[mt][0] = As[m][tig];
            af[mt][1] = As[m + 8][tig];
            af[mt][2] = As[m][tig + 4];
            af[mt][3] = As[m + 8][tig + 4];
        }
#pragma unroll
        for (int nt = 0; nt < 4; nt++) {
            const int n = warpN * 32 + nt * 8 + gid;
            bf[nt][0] = Bs[n][tig];
            bf[nt][1] = Bs[n][tig + 4];
        }
#pragma unroll
        for (int mt = 0; mt < 4; mt++)
#pragma unroll
            for (int nt = 0; nt < 4; nt++)
                mma16(acc[mt][nt], af[mt], bf[nt][0], bf[nt][1]);

        __syncthreads();
    }

    // epilogue
#pragma unroll
    for (int mt = 0; mt < 4; mt++) {
        const int m0 = rowBase + warpM * 64 + mt * 16 + gid;
#pragma unroll
        for (int nt = 0; nt < 4; nt++) {
            const int n = colBase + warpN * 32 + nt * 8 + 2 * tig;
            const float b0 = bias[n];
            const float b1 = bias[n + 1];
            if (mode == 0) {
                const int seg = n / Ff;              // 0:q 1:k 2:v
                __half* dst = (seg == 0) ? g_q : (seg == 1) ? g_k : g_v;
                const int ln = n - seg * Ff;
                *(unsigned*)(dst + (size_t)m0 * Ff + ln) =
                    pack2(acc[mt][nt][0] + b0, acc[mt][nt][1] + b1);
                *(unsigned*)(dst + (size_t)(m0 + 8) * Ff + ln) =
                    pack2(acc[mt][nt][2] + b0, acc[mt][nt][3] + b1);
            } else {
                *(float2*)(C + (size_t)m0 * N + n) =
                    make_float2(acc[mt][nt][0] + b0, acc[mt][nt][1] + b1);
                *(float2*)(C + (size_t)(m0 + 8) * N + n) =
                    make_float2(acc[mt][nt][2] + b0, acc[mt][nt][3] + b1);
            }
        }
    }
}

// ---------------------------------------------------------------------------
// Kernel 2: FP16 flash attention, causal.
// CTA: 128 q-rows, 8 warps (16 q-rows each), 64-key tiles, D=64.
// Q fragments in registers for the whole kernel. K-frags: direct half2 LDS
// from Ks[key][d] (pitch 36 words -> conflict-free). V-frags: ldmatrix.x4
// .trans from Vs[k][d] (144B rows -> conflict-free phases).
// P.V A-fragments = softmaxed QK^T output regs packed to half2 (NO smem
// round-trip). Next tile's K/V/pad prefetched into regs during compute.
// ---------------------------------------------------------------------------
#define KP 36   // Ks/Vs pitch in 32-bit words (= 72 halves = 144 bytes)

__global__ __launch_bounds__(256, 2)
void flash_h(const unsigned char* __restrict__ padmask)
{
    __shared__ unsigned Ks[64][KP];
    __shared__ unsigned Vs[64][KP];
    __shared__ float padAdd[64];

    const int tid  = threadIdx.x;
    const int lane = tid & 31;
    const int w    = tid >> 5;
    const int gid  = lane >> 2;
    const int tig  = lane & 3;

    const int bh = blockIdx.y;
    const int b  = bh / Hh;
    const int h  = bh % Hh;
    const int qt = gridDim.x - 1 - blockIdx.x;      // longest CTAs first
    const int qBase = qt * 128;
    const int qRow0 = qBase + w * 16;

    const __half* Qg = g_q + (size_t)b * Ss * Ff + h * Dd;
    const __half* Kg = g_k + (size_t)b * Ss * Ff + h * Dd;
    const __half* Vg = g_v + (size_t)b * Ss * Ff + h * Dd;
    const unsigned char* pm = padmask + (size_t)b * Ss;

    // ---- Q a-fragments straight from gmem (once per CTA) ----
    unsigned qa[4][4];
    {
        const __half* qr0 = Qg + (size_t)(qRow0 + gid) * Ff;
        const __half* qr1 = Qg + (size_t)(qRow0 + gid + 8) * Ff;
#pragma unroll
        for (int t8 = 0; t8 < 4; t8++) {
            qa[t8][0] = *(const unsigned*)(qr0 + 16 * t8 + 2 * tig);
            qa[t8][1] = *(const unsigned*)(qr1 + 16 * t8 + 2 * tig);
            qa[t8][2] = *(const unsigned*)(qr0 + 16 * t8 + 8 + 2 * tig);
            qa[t8][3] = *(const unsigned*)(qr1 + 16 * t8 + 8 + 2 * tig);
        }
    }

    // per-lane ldmatrix source offset within the V tile
    const int koff  = (lane & 7) + 8 * ((lane >> 3) & 1);
    const int doff  = 8 * (lane >> 4);
    const uint32_t vlane = smem_u32(Vs) + (uint32_t)(koff * (KP * 4) + doff * 2);

    float o[8][4];
#pragma unroll
    for (int j = 0; j < 8; j++)
#pragma unroll
        for (int r = 0; r < 4; r++) o[j][r] = 0.f;
    float mlo = -1e30f, mhi = -1e30f, llo = 0.f, lhi = 0.f;

    const float SC = 0.125f * 1.4426950408889634f;  // 1/sqrt(D) * log2(e)
    const int nkt = (qBase + 128) / 64;             // causal tile count

    // loader mapping: thread -> 2 rows-of-8-uint4 positions per matrix
    const int r0i = tid >> 3, c0 = (tid & 7) * 4;          // idx = tid
    const int r1i = (tid + 256) >> 3, c1 = ((tid + 256) & 7) * 4;

    // prefetch tile 0
    uint4 kr0 = *(const uint4*)(Kg + (size_t)r0i * Ff + 2 * c0);
    uint4 kr1 = *(const uint4*)(Kg + (size_t)r1i * Ff + 2 * c1);
    uint4 vr0 = *(const uint4*)(Vg + (size_t)r0i * Ff + 2 * c0);
    uint4 vr1 = *(const uint4*)(Vg + (size_t)r1i * Ff + 2 * c1);
    unsigned char pb = (tid < 64) ? pm[tid] : (unsigned char)0;

#pragma unroll 1
    for (int kt = 0; kt < nkt; kt++) {
        const int kBase = kt * 64;

        // ---- stage tile kt ----
        *(uint4*)&Ks[r0i][c0] = kr0;
        *(uint4*)&Ks[r1i][c1] = kr1;
        *(uint4*)&Vs[r0i][c0] = vr0;
        *(uint4*)&Vs[r1i][c1] = vr1;
        if (tid < 64) padAdd[tid] = pb ? -1e30f : 0.f;
        __syncthreads();

        // ---- prefetch tile kt+1 (overlaps compute) ----
        if (kt + 1 < nkt) {
            const int nb = kBase + 64;
            kr0 = *(const uint4*)(Kg + (size_t)(nb + r0i) * Ff + 2 * c0);
            kr1 = *(const uint4*)(Kg + (size_t)(nb + r1i) * Ff + 2 * c1);
            vr0 = *(const uint4*)(Vg + (size_t)(nb + r0i) * Ff + 2 * c0);
            vr1 = *(const uint4*)(Vg + (size_t)(nb + r1i) * Ff + 2 * c1);
            pb = (tid < 64) ? pm[nb + tid] : (unsigned char)0;
        }

        const bool active = (kBase <= qRow0 + 15);
        if (active) {
            // ---- S = Q K^T ----
            float s[8][4];
#pragma unroll
            for (int j = 0; j < 8; j++)
#pragma unroll
                for (int r = 0; r < 4; r++) s[j][r] = 0.f;

#pragma unroll
            for (int t8 = 0; t8 < 4; t8++) {
#pragma unroll
                for (int j = 0; j < 8; j++) {
                    const unsigned b0 = Ks[8 * j + gid][8 * t8 + tig];
                    const unsigned b1 = Ks[8 * j + gid][8 * t8 + tig + 4];
                    mma16(s[j], qa[t8], b0, b1);
                }
            }

            // ---- scale + padding + causal mask (fp32) ----
            const int qlo = qRow0 + gid;
            const int qhi = qlo + 8;
            if (kBase + 63 > qRow0) {            // warp-uniform: diagonal tile
#pragma unroll
                for (int j = 0; j < 8; j++) {
                    const float pv0 = padAdd[8 * j + 2 * tig];
                    const float pv1 = padAdd[8 * j + 2 * tig + 1];
                    const int k0 = kBase + 8 * j + 2 * tig;
                    const int k1 = k0 + 1;
                    s[j][0] = (k0 > qlo) ? -1e30f : fmaf(s[j][0], SC, pv0);
                    s[j][1] = (k1 > qlo) ? -1e30f : fmaf(s[j][1], SC, pv1);
                    s[j][2] = (k0 > qhi) ? -1e30f : fmaf(s[j][2], SC, pv0);
                    s[j][3] = (k1 > qhi) ? -1e30f : fmaf(s[j][3], SC, pv1);
                }
            } else {
#pragma unroll
                for (int j = 0; j < 8; j++) {
                    const float pv0 = padAdd[8 * j + 2 * tig];
                    const float pv1 = padAdd[8 * j + 2 * tig + 1];
                    s[j][0] = fmaf(s[j][0], SC, pv0);
                    s[j][1] = fmaf(s[j][1], SC, pv1);
                    s[j][2] = fmaf(s[j][2], SC, pv0);
                    s[j][3] = fmaf(s[j][3], SC, pv1);
                }
            }

            // ---- online softmax (rows owned by 4-lane quads) ----
            float mtlo = -1e30f, mthi = -1e30f;
#pragma unroll
            for (int j = 0; j < 8; j++) {
                mtlo = fmaxf(mtlo, fmaxf(s[j][0], s[j][1]));
                mthi = fmaxf(mthi, fmaxf(s[j][2], s[j][3]));
            }
            mtlo = fmaxf(mtlo, __shfl_xor_sync(0xffffffffu, mtlo, 1));
            mtlo = fmaxf(mtlo, __shfl_xor_sync(0xffffffffu, mtlo, 2));
            mthi = fmaxf(mthi, __shfl_xor_sync(0xffffffffu, mthi, 1));
            mthi = fmaxf(mthi, __shfl_xor_sync(0xffffffffu, mthi, 2));

            const float mnl = fmaxf(mlo, mtlo);
            const float mnh = fmaxf(mhi, mthi);
            const float clo = exp2f(mlo - mnl);
            const float chi = exp2f(mhi - mnh);
            mlo = mnl; mhi = mnh;

            float rslo = 0.f, rshi = 0.f;
#pragma unroll
            for (int j = 0; j < 8; j++) {
                s[j][0] = exp2f(s[j][0] - mnl);
                s[j][1] = exp2f(s[j][1] - mnl);
                s[j][2] = exp2f(s[j][2] - mnh);
                s[j][3] = exp2f(s[j][3] - mnh);
                rslo += s[j][0] + s[j][1];
                rshi += s[j][2] + s[j][3];
            }
            rslo += __shfl_xor_sync(0xffffffffu, rslo, 1);
            rslo += __shfl_xor_sync(0xffffffffu, rslo, 2);
            rshi += __shfl_xor_sync(0xffffffffu, rshi, 1);
            rshi += __shfl_xor_sync(0xffffffffu, rshi, 2);
            llo = llo * clo + rslo;
            lhi = lhi * chi + rshi;
#pragma unroll
            for (int j = 0; j < 8; j++) {
                o[j][0] *= clo; o[j][1] *= clo;
                o[j][2] *= chi; o[j][3] *= chi;
            }

            // ---- O += P V : A-frags are the packed s-registers ----
#pragma unroll
            for (int t8 = 0; t8 < 4; t8++) {
                unsigned pa[4];
                pa[0] = pack2(s[2 * t8][0],     s[2 * t8][1]);
                pa[1] = pack2(s[2 * t8][2],     s[2 * t8][3]);
                pa[2] = pack2(s[2 * t8 + 1][0], s[2 * t8 + 1][1]);
                pa[3] = pack2(s[2 * t8 + 1][2], s[2 * t8 + 1][3]);
#pragma unroll
                for (int dj = 0; dj < 8; dj += 2) {
                    unsigned v0, v1, v2, v3;
                    LDSM_X4_T(v0, v1, v2, v3,
                              vlane + t8 * 16 * (KP * 4) + dj * 16);
                    mma16(o[dj],     pa, v0, v1);
                    mma16(o[dj + 1], pa, v2, v3);
                }
            }
        }
        __syncthreads();
    }

    // ---- finalize: O /= l, write [B,S,H,D] as fp16 ----
    const float ilo = 1.0f / llo;
    const float ihi = 1.0f / lhi;
    const int qlo = qRow0 + gid;
    __half* Og = g_attn + (size_t)b * Ss * Ff + h * Dd;
#pragma unroll
    for (int j = 0; j < 8; j++) {
        const int d = 8 * j + 2 * tig;
        *(unsigned*)(Og + (size_t)qlo * Ff + d) =
            pack2(o[j][0] * ilo, o[j][1] * ilo);
        *(unsigned*)(Og + (size_t)(qlo + 8) * Ff + d) =
            pack2(o[j][2] * ihi, o[j][3] * ihi);
    }
}

// ---------------------------------------------------------------------------
// Launch: convert/transpose -> QKV gemm -> flash -> out gemm
// ---------------------------------------------------------------------------
extern "C" void kernel_launch(void* const* d_in, const int* in_sizes, int n_in,
                              void* d_out, int out_size)
{
    (void)in_sizes; (void)n_in; (void)out_size;
    const float*         x    = (const float*)d_in[0];
    const unsigned char* pad  = (const unsigned char*)d_in[1];
    const float*         Wqkv = (const float*)d_in[2];
    const float*         bqkv = (const float*)d_in[3];
    const float*         Wout = (const float*)d_in[4];
    const float*         bout = (const float*)d_in[5];
    float*               out  = (float*)d_out;

    __half *xh = nullptr, *WqkvT = nullptr, *WoutT = nullptr, *attnPtr = nullptr;
    cudaGetSymbolAddress((void**)&xh, g_xh);
    cudaGetSymbolAddress((void**)&WqkvT, g_WqkvT);
    cudaGetSymbolAddress((void**)&WoutT, g_WoutT);
    cudaGetSymbolAddress((void**)&attnPtr, g_attn);

    // 0) x -> fp16; weight transpose+convert
    f2h_kernel<<<(ROWS * Ff) / 1024, 256>>>(x, xh);
    {
        dim3 g1(NQKV / 32, Ff / 32);             // (72, 24)
        transpose_kn_h<<<g1, 256>>>(Wqkv, WqkvT, Ff, NQKV);
        dim3 g2(Ff / 32, Ff / 32);               // (24, 24)
        transpose_kn_h<<<g2, 256>>>(Wout, WoutT, Ff, Ff);
    }

    // 1) QKV projection (fp16 mma): [8192,768]@[768,2304] -> g_q/g_k/g_v
    {
        dim3 grid(NQKV / 128, ROWS / 128);       // (18, 64)
        gemm_h<<<grid, 256>>>(xh, WqkvT, bqkv, nullptr, Ff, NQKV, 0);
    }

    // 2) causal flash attention (fp16 mma) -> g_attn
    {
        dim3 grid(Ss / 128, Bb * Hh);            // (32, 24)
        flash_h<<<grid, 256>>>(pad);
    }

    // 3) output projection: g_attn @ Wout + bout -> d_out (float)
    {
        dim3 grid(Ff / 128, ROWS / 128);         // (6, 64)
        gemm_h<<<grid, 256>>>(attnPtr, WoutT, bout, out, Ff, Ff, 1);
    }
}

// round 12
// speedup vs baseline: 1.9891x; 1.0185x over previous
#include <cuda_runtime.h>
#include <cuda_fp16.h>
#include <cstdint>
#include <cstddef>

// ---------------------------------------------------------------------------
// Problem dims (fixed by the reference)
// ---------------------------------------------------------------------------
#define Bb   2
#define Ss   4096
#define Ff   768
#define Hh   12
#define Dd   64
#define ROWS (Bb * Ss)          // 8192 token rows
#define NQKV (3 * Ff)           // 2304

// ---------------------------------------------------------------------------
// Scratch (device globals: allocation-free rule). All intermediates fp16.
// ---------------------------------------------------------------------------
__device__ __half g_xh[ROWS * Ff];     // x converted to fp16
__device__ __half g_q[ROWS * Ff];      // [B,S,H,D]
__device__ __half g_k[ROWS * Ff];
__device__ __half g_v[ROWS * Ff];
__device__ __half g_attn[ROWS * Ff];   // attention output [B,S,H,D]
__device__ __half g_WqkvT[NQKV * Ff];  // Wqkv^T [2304][768] fp16
__device__ __half g_WoutT[Ff * Ff];    // Wout^T [768][768] fp16

// ---------------------------------------------------------------------------
// Helpers
// ---------------------------------------------------------------------------
__device__ __forceinline__ unsigned pack2(float a, float b) {
    __half2 h = __floats2half2_rn(a, b);
    return *reinterpret_cast<unsigned*>(&h);
}

// D(16x8,f32) += A(16x16,f16) * B(16x8,f16)
__device__ __forceinline__ void mma16(float* c, const unsigned* a,
                                      unsigned b0, unsigned b1) {
    asm volatile(
        "mma.sync.aligned.m16n8k16.row.col.f32.f16.f16.f32 "
        "{%0,%1,%2,%3}, {%4,%5,%6,%7}, {%8,%9}, {%0,%1,%2,%3};"
        : "+f"(c[0]), "+f"(c[1]), "+f"(c[2]), "+f"(c[3])
        : "r"(a[0]), "r"(a[1]), "r"(a[2]), "r"(a[3]), "r"(b0), "r"(b1));
}

#define LDSM_X4(r0, r1, r2, r3, addr)                                         \
    asm volatile(                                                             \
        "ldmatrix.sync.aligned.m8n8.x4.shared.b16 {%0,%1,%2,%3}, [%4];"       \
        : "=r"(r0), "=r"(r1), "=r"(r2), "=r"(r3) : "r"(addr))

#define LDSM_X4_T(r0, r1, r2, r3, addr)                                       \
    asm volatile(                                                             \
        "ldmatrix.sync.aligned.m8n8.x4.trans.shared.b16 {%0,%1,%2,%3}, [%4];" \
        : "=r"(r0), "=r"(r1), "=r"(r2), "=r"(r3) : "r"(addr))

__device__ __forceinline__ uint32_t smem_u32(const void* p) {
    uint32_t a;
    asm("{ .reg .u64 t; cvta.to.shared.u64 t, %1; cvt.u32.u64 %0, t; }"
        : "=r"(a) : "l"(p));
    return a;
}

// ---------------------------------------------------------------------------
// Kernel A: float -> half bulk convert (for x)
// ---------------------------------------------------------------------------
__global__ __launch_bounds__(256)
void f2h_kernel(const float* __restrict__ s, __half* __restrict__ d)
{
    const size_t i = ((size_t)blockIdx.x * 256 + threadIdx.x) * 4;
    float4 v = *(const float4*)(s + i);
    *(uint2*)(d + i) = make_uint2(pack2(v.x, v.y), pack2(v.z, v.w));
}

// ---------------------------------------------------------------------------
// Kernel B: transpose W[K][N] (f32) -> WT[N][K] (f16)
// ---------------------------------------------------------------------------
__global__ __launch_bounds__(256)
void transpose_kn_h(const float* __restrict__ W, __half* __restrict__ WT,
                    int K, int N)
{
    __shared__ float t[32][33];
    const int tx = threadIdx.x & 31, ty = threadIdx.x >> 5;
    const int n0 = blockIdx.x * 32, k0 = blockIdx.y * 32;
#pragma unroll
    for (int i = 0; i < 4; i++)
        t[ty + 8 * i][tx] = W[(size_t)(k0 + ty + 8 * i) * N + n0 + tx];
    __syncthreads();
#pragma unroll
    for (int i = 0; i < 4; i++)
        WT[(size_t)(n0 + ty + 8 * i) * K + k0 + tx] =
            __float2half(t[tx][ty + 8 * i]);
}

// ---------------------------------------------------------------------------
// Kernel 1 & 3: FP16 m16n8k16 GEMM, 128x128 tile, BK=16, 256 threads,
// DOUBLE-BUFFERED smem (one __syncthreads per iter), ldmatrix fragments.
// A[m][k] f16 row-major, BT[n][k] f16 row-major. Warps 2(M)x4(N), 4x4 tiles.
// Pitch 12 words (48B)/row: every 8-lane ldsm phase hits 8 distinct 16B
// banks -> conflict-free.
// mode 0: C half, split into g_q/g_k/g_v (N==2304). mode 1: C float + bias.
// ---------------------------------------------------------------------------
__global__ __launch_bounds__(256, 2)
void gemm_h(const __half* __restrict__ A, const __half* __restrict__ BT,
            const float* __restrict__ bias, float* __restrict__ C,
            int K, int N, int mode)
{
    __shared__ unsigned As[2][128][12];
    __shared__ unsigned Bs[2][128][12];
    const uint32_t BUF = 128 * 12 * 4;           // 6144 B per buffer

    const int tid  = threadIdx.x;
    const int lane = tid & 31;
    const int wid  = tid >> 5;
    const int gid  = lane >> 2;      // 0..7
    const int tig  = lane & 3;       // 0..3
    const int warpM = wid & 1;
    const int warpN = wid >> 1;

    const int rowBase = blockIdx.y * 128;
    const int colBase = blockIdx.x * 128;

    // gmem loaders: thread -> (row tid>>1, uint4 half tid&1)
    const int aRow = tid >> 1;
    const int aC   = tid & 1;
    const __half* Ap = A  + (size_t)(rowBase + aRow) * K + aC * 8;
    const __half* Bp = BT + (size_t)(colBase + aRow) * K + aC * 8;

    // ldmatrix per-lane addresses (within buffer 0)
    const uint32_t aSm = smem_u32(As);
    const uint32_t bSm = smem_u32(Bs);
    const int g8 = lane >> 3;                    // 0..3
    const uint32_t aOff = (uint32_t)(((warpM * 64 + (lane & 15)) * 12 +
                                      (lane >> 4) * 4) * 4);
    const uint32_t bOff = (uint32_t)(((warpN * 32 + (g8 >> 1) * 8 + (lane & 7)) * 12 +
                                      (g8 & 1) * 4) * 4);

    float acc[4][4][4];
#pragma unroll
    for (int mt = 0; mt < 4; mt++)
#pragma unroll
        for (int nt = 0; nt < 4; nt++)
#pragma unroll
            for (int r = 0; r < 4; r++) acc[mt][nt][r] = 0.f;

    // preload tile 0 -> buffer 0
    {
        uint4 ra = *(const uint4*)Ap;
        uint4 rb = *(const uint4*)Bp;
        *(uint4*)&As[0][aRow][aC * 4] = ra;
        *(uint4*)&Bs[0][aRow][aC * 4] = rb;
    }
    __syncthreads();

    const int nIter = K / 16;
#pragma unroll 1
    for (int it = 0; it < nIter; it++) {
        const int cur = it & 1;
        const bool more = (it + 1 < nIter);
        uint4 ra, rb;
        if (more) {
            ra = *(const uint4*)(Ap + (it + 1) * 16);
            rb = *(const uint4*)(Bp + (it + 1) * 16);
        }

        // ---- fragments via ldmatrix ----
        unsigned af[4][4], bf[4][2];
#pragma unroll
        for (int mt = 0; mt < 4; mt++)
            LDSM_X4(af[mt][0], af[mt][1], af[mt][2], af[mt][3],
                    aSm + cur * BUF + aOff + mt * 768);   // 16 rows * 48B
        LDSM_X4(bf[0][0], bf[0][1], bf[1][0], bf[1][1], bSm + cur * BUF + bOff);
        LDSM_X4(bf[2][0], bf[2][1], bf[3][0], bf[3][1],
                bSm + cur * BUF + bOff + 768);            // +16 n-rows

#pragma unroll
        for (int mt = 0; mt < 4; mt++)
#pragma unroll
            for (int nt = 0; nt < 4; nt++)
                mma16(acc[mt][nt], af[mt], bf[nt][0], bf[nt][1]);

        if (more) {
            *(uint4*)&As[cur ^ 1][aRow][aC * 4] = ra;
            *(uint4*)&Bs[cur ^ 1][aRow][aC * 4] = rb;
        }
        __syncthreads();
    }

    // epilogue
#pragma unroll
    for (int mt = 0; mt < 4; mt++) {
        const int m0 = rowBase + warpM * 64 + mt * 16 + gid;
#pragma unroll
        for (int nt = 0; nt < 4; nt++) {
            const int n = colBase + warpN * 32 + nt * 8 + 2 * tig;
            const float b0 = bias[n];
            const float b1 = bias[n + 1];
            if (mode == 0) {
                const int seg = n / Ff;              // 0:q 1:k 2:v
                __half* dst = (seg == 0) ? g_q : (seg == 1) ? g_k : g_v;
                const int ln = n - seg * Ff;
                *(unsigned*)(dst + (size_t)m0 * Ff + ln) =
                    pack2(acc[mt][nt][0] + b0, acc[mt][nt][1] + b1);
                *(unsigned*)(dst + (size_t)(m0 + 8) * Ff + ln) =
                    pack2(acc[mt][nt][2] + b0, acc[mt][nt][3] + b1);
            } else {
                *(float2*)(C + (size_t)m0 * N + n) =
                    make_float2(acc[mt][nt][0] + b0, acc[mt][nt][1] + b1);
                *(float2*)(C + (size_t)(m0 + 8) * N + n) =
                    make_float2(acc[mt][nt][2] + b0, acc[mt][nt][3] + b1);
            }
        }
    }
}

// ---------------------------------------------------------------------------
// Kernel 2: FP16 flash attention, causal.
// CTA: 128 q-rows, 8 warps (16 q-rows each), 64-key tiles, D=64.
// Q fragments in registers for the whole kernel. K-frags AND V-frags via
// ldmatrix (K non-trans, V trans); pitch 36 words (144B) -> conflict-free.
// P.V A-fragments = softmaxed QK^T regs packed to half2 (no smem round-trip).
// Next tile's K/V/pad prefetched into registers during compute.
// ---------------------------------------------------------------------------
#define KP 36   // Ks/Vs pitch in 32-bit words (= 72 halves = 144 bytes)

__global__ __launch_bounds__(256, 2)
void flash_h(const unsigned char* __restrict__ padmask)
{
    __shared__ unsigned Ks[64][KP];
    __shared__ unsigned Vs[64][KP];
    __shared__ float padAdd[64];

    const int tid  = threadIdx.x;
    const int lane = tid & 31;
    const int w    = tid >> 5;
    const int gid  = lane >> 2;
    const int tig  = lane & 3;

    const int bh = blockIdx.y;
    const int b  = bh / Hh;
    const int h  = bh % Hh;
    const int qt = gridDim.x - 1 - blockIdx.x;      // longest CTAs first
    const int qBase = qt * 128;
    const int qRow0 = qBase + w * 16;

    const __half* Qg = g_q + (size_t)b * Ss * Ff + h * Dd;
    const __half* Kg = g_k + (size_t)b * Ss * Ff + h * Dd;
    const __half* Vg = g_v + (size_t)b * Ss * Ff + h * Dd;
    const unsigned char* pm = padmask + (size_t)b * Ss;

    // ---- Q a-fragments straight from gmem (once per CTA) ----
    unsigned qa[4][4];
    {
        const __half* qr0 = Qg + (size_t)(qRow0 + gid) * Ff;
        const __half* qr1 = Qg + (size_t)(qRow0 + gid + 8) * Ff;
#pragma unroll
        for (int t8 = 0; t8 < 4; t8++) {
            qa[t8][0] = *(const unsigned*)(qr0 + 16 * t8 + 2 * tig);
            qa[t8][1] = *(const unsigned*)(qr1 + 16 * t8 + 2 * tig);
            qa[t8][2] = *(const unsigned*)(qr0 + 16 * t8 + 8 + 2 * tig);
            qa[t8][3] = *(const unsigned*)(qr1 + 16 * t8 + 8 + 2 * tig);
        }
    }

    // ldmatrix lane addresses
    // K (non-trans): matrix g8 = d-chunk; row = key (lane&7), col = g8*8 halves
    const int g8 = lane >> 3;
    const uint32_t kAddr = smem_u32(Ks) +
        (uint32_t)((lane & 7) * (KP * 4) + g8 * 16);
    // V (trans): row = key, col = d-chunk
    const int koff = (lane & 7) + 8 * ((lane >> 3) & 1);
    const int doff = 8 * (lane >> 4);
    const uint32_t vAddr = smem_u32(Vs) +
        (uint32_t)(koff * (KP * 4) + doff * 2);

    float o[8][4];
#pragma unroll
    for (int j = 0; j < 8; j++)
#pragma unroll
        for (int r = 0; r < 4; r++) o[j][r] = 0.f;
    float mlo = -1e30f, mhi = -1e30f, llo = 0.f, lhi = 0.f;

    const float SC = 0.125f * 1.4426950408889634f;  // 1/sqrt(D) * log2(e)
    const int nkt = (qBase + 128) / 64;             // causal tile count

    // gmem loader mapping: 2 uint4 rows-of-8 per matrix
    const int r0i = tid >> 3, c0 = (tid & 7) * 4;
    const int r1i = (tid + 256) >> 3, c1 = ((tid + 256) & 7) * 4;

    // prefetch tile 0
    uint4 kr0 = *(const uint4*)(Kg + (size_t)r0i * Ff + 2 * c0);
    uint4 kr1 = *(const uint4*)(Kg + (size_t)r1i * Ff + 2 * c1);
    uint4 vr0 = *(const uint4*)(Vg + (size_t)r0i * Ff + 2 * c0);
    uint4 vr1 = *(const uint4*)(Vg + (size_t)r1i * Ff + 2 * c1);
    unsigned char pb = (tid < 64) ? pm[tid] : (unsigned char)0;

#pragma unroll 1
    for (int kt = 0; kt < nkt; kt++) {
        const int kBase = kt * 64;

        // ---- stage tile kt ----
        *(uint4*)&Ks[r0i][c0] = kr0;
        *(uint4*)&Ks[r1i][c1] = kr1;
        *(uint4*)&Vs[r0i][c0] = vr0;
        *(uint4*)&Vs[r1i][c1] = vr1;
        if (tid < 64) padAdd[tid] = pb ? -1e30f : 0.f;
        __syncthreads();

        // ---- prefetch tile kt+1 (overlaps compute) ----
        if (kt + 1 < nkt) {
            const int nb = kBase + 64;
            kr0 = *(const uint4*)(Kg + (size_t)(nb + r0i) * Ff + 2 * c0);
            kr1 = *(const uint4*)(Kg + (size_t)(nb + r1i) * Ff + 2 * c1);
            vr0 = *(const uint4*)(Vg + (size_t)(nb + r0i) * Ff + 2 * c0);
            vr1 = *(const uint4*)(Vg + (size_t)(nb + r1i) * Ff + 2 * c1);
            pb = (tid < 64) ? pm[nb + tid] : (unsigned char)0;
        }

        const bool active = (kBase <= qRow0 + 15);
        if (active) {
            // ---- S = Q K^T (K-frags via ldmatrix) ----
            float s[8][4];
#pragma unroll
            for (int j = 0; j < 8; j++)
#pragma unroll
                for (int r = 0; r < 4; r++) s[j][r] = 0.f;

#pragma unroll
            for (int j = 0; j < 8; j++) {
                unsigned kb[8];
                const uint32_t ja = kAddr + (uint32_t)(j * 8 * (KP * 4));
                LDSM_X4(kb[0], kb[1], kb[2], kb[3], ja);        // d 0..31
                LDSM_X4(kb[4], kb[5], kb[6], kb[7], ja + 64);   // d 32..63
#pragma unroll
                for (int t8 = 0; t8 < 4; t8++)
                    mma16(s[j], qa[t8], kb[2 * t8], kb[2 * t8 + 1]);
            }

            // ---- scale + padding + causal mask (fp32) ----
            const int qlo = qRow0 + gid;
            const int qhi = qlo + 8;
            if (kBase + 63 > qRow0) {            // warp-uniform: diagonal tile
#pragma unroll
                for (int j = 0; j < 8; j++) {
                    const float pv0 = padAdd[8 * j + 2 * tig];
                    const float pv1 = padAdd[8 * j + 2 * tig + 1];
                    const int k0 = kBase + 8 * j + 2 * tig;
                    const int k1 = k0 + 1;
                    s[j][0] = (k0 > qlo) ? -1e30f : fmaf(s[j][0], SC, pv0);
                    s[j][1] = (k1 > qlo) ? -1e30f : fmaf(s[j][1], SC, pv1);
                    s[j][2] = (k0 > qhi) ? -1e30f : fmaf(s[j][2], SC, pv0);
                    s[j][3] = (k1 > qhi) ? -1e30f : fmaf(s[j][3], SC, pv1);
                }
            } else {
#pragma unroll
                for (int j = 0; j < 8; j++) {
                    const float pv0 = padAdd[8 * j + 2 * tig];
                    const float pv1 = padAdd[8 * j + 2 * tig + 1];
                    s[j][0] = fmaf(s[j][0], SC, pv0);
                    s[j][1] = fmaf(s[j][1], SC, pv1);
                    s[j][2] = fmaf(s[j][2], SC, pv0);
                    s[j][3] = fmaf(s[j][3], SC, pv1);
                }
            }

            // ---- online softmax (rows owned by 4-lane quads) ----
            float mtlo = -1e30f, mthi = -1e30f;
#pragma unroll
            for (int j = 0; j < 8; j++) {
                mtlo = fmaxf(mtlo, fmaxf(s[j][0], s[j][1]));
                mthi = fmaxf(mthi, fmaxf(s[j][2], s[j][3]));
            }
            mtlo = fmaxf(mtlo, __shfl_xor_sync(0xffffffffu, mtlo, 1));
            mtlo = fmaxf(mtlo, __shfl_xor_sync(0xffffffffu, mtlo, 2));
            mthi = fmaxf(mthi, __shfl_xor_sync(0xffffffffu, mthi, 1));
            mthi = fmaxf(mthi, __shfl_xor_sync(0xffffffffu, mthi, 2));

            const float mnl = fmaxf(mlo, mtlo);
            const float mnh = fmaxf(mhi, mthi);
            const float clo = exp2f(mlo - mnl);
            const float chi = exp2f(mhi - mnh);
            mlo = mnl; mhi = mnh;

            float rslo = 0.f, rshi = 0.f;
#pragma unroll
            for (int j = 0; j < 8; j++) {
                s[j][0] = exp2f(s[j][0] - mnl);
                s[j][1] = exp2f(s[j][1] - mnl);
                s[j][2] = exp2f(s[j][2] - mnh);
                s[j][3] = exp2f(s[j][3] - mnh);
                rslo += s[j][0] + s[j][1];
                rshi += s[j][2] + s[j][3];
            }
            rslo += __shfl_xor_sync(0xffffffffu, rslo, 1);
            rslo += __shfl_xor_sync(0xffffffffu, rslo, 2);
            rshi += __shfl_xor_sync(0xffffffffu, rshi, 1);
            rshi += __shfl_xor_sync(0xffffffffu, rshi, 2);
            llo = llo * clo + rslo;
            lhi = lhi * chi + rshi;
#pragma unroll
            for (int j = 0; j < 8; j++) {
                o[j][0] *= clo; o[j][1] *= clo;
                o[j][2] *= chi; o[j][3] *= chi;
            }

            // ---- O += P V : A-frags are the packed s-registers ----
#pragma unroll
            for (int t8 = 0; t8 < 4; t8++) {
                unsigned pa[4];
                pa[0] = pack2(s[2 * t8][0],     s[2 * t8][1]);
                pa[1] = pack2(s[2 * t8][2],     s[2 * t8][3]);
                pa[2] = pack2(s[2 * t8 + 1][0], s[2 * t8 + 1][1]);
                pa[3] = pack2(s[2 * t8 + 1][2], s[2 * t8 + 1][3]);
#pragma unroll
                for (int dj = 0; dj < 8; dj += 2) {
                    unsigned v0, v1, v2, v3;
                    LDSM_X4_T(v0, v1, v2, v3,
                              vAddr + t8 * 16 * (KP * 4) + dj * 16);
                    mma16(o[dj],     pa, v0, v1);
                    mma16(o[dj + 1], pa, v2, v3);
                }
            }
        }
        __syncthreads();
    }

    // ---- finalize: O /= l, write [B,S,H,D] as fp16 ----
    const float ilo = 1.0f / llo;
    const float ihi = 1.0f / lhi;
    const int qlo = qRow0 + gid;
    __half* Og = g_attn + (size_t)b * Ss * Ff + h * Dd;
#pragma unroll
    for (int j = 0; j < 8; j++) {
        const int d = 8 * j + 2 * tig;
        *(unsigned*)(Og + (size_t)qlo * Ff + d) =
            pack2(o[j][0] * ilo, o[j][1] * ilo);
        *(unsigned*)(Og + (size_t)(qlo + 8) * Ff + d) =
            pack2(o[j][2] * ihi, o[j][3] * ihi);
    }
}

// ---------------------------------------------------------------------------
// Launch: convert/transpose -> QKV gemm -> flash -> out gemm
// ---------------------------------------------------------------------------
extern "C" void kernel_launch(void* const* d_in, const int* in_sizes, int n_in,
                              void* d_out, int out_size)
{
    (void)in_sizes; (void)n_in; (void)out_size;
    const float*         x    = (const float*)d_in[0];
    const unsigned char* pad  = (const unsigned char*)d_in[1];
    const float*         Wqkv = (const float*)d_in[2];
    const float*         bqkv = (const float*)d_in[3];
    const float*         Wout = (const float*)d_in[4];
    const float*         bout = (const float*)d_in[5];
    float*               out  = (float*)d_out;

    __half *xh = nullptr, *WqkvT = nullptr, *WoutT = nullptr, *attnPtr = nullptr;
    cudaGetSymbolAddress((void**)&xh, g_xh);
    cudaGetSymbolAddress((void**)&WqkvT, g_WqkvT);
    cudaGetSymbolAddress((void**)&WoutT, g_WoutT);
    cudaGetSymbolAddress((void**)&attnPtr, g_attn);

    // 0) x -> fp16; weight transpose+convert
    f2h_kernel<<<(ROWS * Ff) / 1024, 256>>>(x, xh);
    {
        dim3 g1(NQKV / 32, Ff / 32);             // (72, 24)
        transpose_kn_h<<<g1, 256>>>(Wqkv, WqkvT, Ff, NQKV);
        dim3 g2(Ff / 32, Ff / 32);               // (24, 24)
        transpose_kn_h<<<g2, 256>>>(Wout, WoutT, Ff, Ff);
    }

    // 1) QKV projection (fp16 mma): [8192,768]@[768,2304] -> g_q/g_k/g_v
    {
        dim3 grid(NQKV / 128, ROWS / 128);       // (18, 64)
        gemm_h<<<grid, 256>>>(xh, WqkvT, bqkv, nullptr, Ff, NQKV, 0);
    }

    // 2) causal flash attention (fp16 mma) -> g_attn
    {
        dim3 grid(Ss / 128, Bb * Hh);            // (32, 24)
        flash_h<<<grid, 256>>>(pad);
    }

    // 3) output projection: g_attn @ Wout + bout -> d_out (float)
    {
        dim3 grid(Ff / 128, ROWS / 128);         // (6, 64)
        gemm_h<<<grid, 256>>>(attnPtr, WoutT, bout, out, Ff, Ff, 1);
    }
}